// round 16
// baseline (speedup 1.0000x reference)
#include <cuda_runtime.h>
#include <math.h>

#define NN 50000
#define NE 600000
#define HH 128
#define EDD 16
#define TDD 32

#define ET 64      // edges per block (edge kernel)
#define PC_NB 8    // nodes per block, precompute (R10 proven)
#define NB 32      // nodes per block (node_out)
#define NBP 36     // padded stride

static_assert(NN % PC_NB == 0, "precompute exact");
static_assert(NE % ET == 0, "edge tile exact");

// ---------------- device scratch ----------------
__device__ float g_A1[NN * HH];
__device__ float g_A2[NN * HH];
__device__ float g_B1[NN * HH];
__device__ float g_B2[NN * HH];
__device__ float g_msg[NN * HH];
__device__ float g_coord[NN * 3];
__device__ int   g_is64;

typedef unsigned long long u64;

__device__ __forceinline__ u64 pk(float lo, float hi) {
    u64 r; asm("mov.b64 %0,{%1,%2};" : "=l"(r) : "f"(lo), "f"(hi)); return r;
}
__device__ __forceinline__ void upk(float& lo, float& hi, u64 v) {
    asm("mov.b64 {%0,%1},%2;" : "=f"(lo), "=f"(hi) : "l"(v));
}
__device__ __forceinline__ u64 f2fma(u64 a, u64 b, u64 c) {
    u64 d; asm("fma.rn.f32x2 %0,%1,%2,%3;" : "=l"(d) : "l"(a), "l"(b), "l"(c)); return d;
}
__device__ __forceinline__ u64 f2add(u64 a, u64 b) {
    u64 d; asm("add.rn.f32x2 %0,%1,%2;" : "=l"(d) : "l"(a), "l"(b)); return d;
}
__device__ __forceinline__ void red2(float* addr, float a, float b) {
    asm volatile("red.global.add.v2.f32 [%0], {%1,%2};" :: "l"(addr), "f"(a), "f"(b) : "memory");
}
__device__ __forceinline__ float silu_f(float v) {
    return v / (1.f + __expf(-v));
}

// ---------------- per-node layer-1 partials (f32x2), PC_NB=8 (R10 proven) ----------------
// Block 0 additionally performs the int32-vs-int64 edge_index detection
// (reads only the first 128 i64 words -> in-bounds for either dtype).
__global__ __launch_bounds__(128)
void precompute_kernel(const float* __restrict__ h, const float* __restrict__ t_emb,
                       const float* __restrict__ We_w1, const float* __restrict__ We_b1,
                       const float* __restrict__ Wx_w1, const float* __restrict__ Wx_b1,
                       const void* __restrict__ ei)
{
    __shared__ float hbufT[HH * PC_NB];
    __shared__ float tbufT[TDD * PC_NB];
    int col = threadIdx.x;
    int n0 = blockIdx.x * PC_NB;

    if (blockIdx.x == 0) {
        __shared__ int ok;
        if (col == 0) ok = 1;
        __syncthreads();
        const long long* p = (const long long*)ei;
        long long v = p[col];
        if (v < 0 || v >= NN) atomicExch(&ok, 0);
        __syncthreads();
        if (col == 0) g_is64 = ok;
    }

    for (int i = col; i < PC_NB * HH; i += 128) {
        int j = i >> 7, k = i & 127;
        hbufT[k * PC_NB + j] = h[(size_t)(n0 + j) * HH + k];
    }
    for (int i = col; i < PC_NB * TDD; i += 128) {
        int j = i >> 5, k = i & 31;
        tbufT[k * PC_NB + j] = t_emb[(size_t)(n0 + j) * TDD + k];
    }
    __syncthreads();

    u64 a1[4], a2[4], b1[4], b2[4];
    {
        float be = We_b1[col], bx = Wx_b1[col];
        u64 pbe = pk(be, be), pbx = pk(bx, bx), z = pk(0.f, 0.f);
#pragma unroll
        for (int j = 0; j < 4; j++) { a1[j] = pbe; b1[j] = pbx; a2[j] = z; b2[j] = z; }
    }
#pragma unroll 4
    for (int k = 0; k < HH; k++) {
        float wa1 = We_w1[(size_t)k * HH + col];
        float wa2 = We_w1[(size_t)(HH + k) * HH + col];
        float wb1 = Wx_w1[(size_t)k * HH + col];
        float wb2 = Wx_w1[(size_t)(HH + k) * HH + col];
        u64 pa1 = pk(wa1, wa1), pa2 = pk(wa2, wa2);
        u64 pb1 = pk(wb1, wb1), pb2 = pk(wb2, wb2);
        const u64* ph = (const u64*)(hbufT + k * PC_NB);
#pragma unroll
        for (int j = 0; j < 4; j++) {
            u64 hv = ph[j];
            a1[j] = f2fma(hv, pa1, a1[j]);
            a2[j] = f2fma(hv, pa2, a2[j]);
            b1[j] = f2fma(hv, pb1, b1[j]);
            b2[j] = f2fma(hv, pb2, b2[j]);
        }
    }
#pragma unroll 4
    for (int k = 0; k < TDD; k++) {
        float wta = We_w1[(size_t)(273 + k) * HH + col];
        float wtb = Wx_w1[(size_t)(272 + k) * HH + col];
        u64 pta = pk(wta, wta), ptb = pk(wtb, wtb);
        const u64* pt = (const u64*)(tbufT + k * PC_NB);
#pragma unroll
        for (int j = 0; j < 4; j++) {
            u64 tv = pt[j];
            a1[j] = f2fma(tv, pta, a1[j]);
            b1[j] = f2fma(tv, ptb, b1[j]);
        }
    }
#pragma unroll
    for (int j = 0; j < 4; j++) {
        size_t o0 = (size_t)(n0 + 2 * j) * HH + col;
        size_t o1 = o0 + HH;
        float x0, x1;
        upk(x0, x1, a1[j]); g_A1[o0] = x0; g_A1[o1] = x1;
        upk(x0, x1, a2[j]); g_A2[o0] = x0; g_A2[o1] = x1;
        upk(x0, x1, b1[j]); g_B1[o0] = x0; g_B1[o1] = x1;
        upk(x0, x1, b2[j]); g_B2[o0] = x0; g_B2[o1] = x1;
        g_msg[o0] = 0.f; g_msg[o1] = 0.f;
    }
    if (col < PC_NB * 3) g_coord[n0 * 3 + col] = 0.f;
}

// ================= merged edge kernel (R10 proven config: occ-3, split-pair float2) =================
// smem float offsets
#define S_W1E   0                    // 17 x 128 (We_w1 rows 256..272)
#define S_W1X   (S_W1E + 2176)       // 16 x 128 (Wx_w1 rows 256..271)
#define S_B2E   (S_W1X + 2048)       // 128
#define S_B2X   (S_B2E + 128)
#define S_WATT  (S_B2X + 128)
#define S_WX3   (S_WATT + 128)
#define S_EXT   (S_WX3 + 128)        // 17 x 64 [row][edge]
#define S_DIFFN (S_EXT + 17*64)      // 3 x 64
#define S_SRC   (S_DIFFN + 192)      // 64 ints
#define S_DST   (S_SRC + 64)
#define S_ACT   (S_DST + 64)         // 128 x 64 [k][edge], reused for both paths
#define S_SIZE  (S_ACT + 128*64)
#define EDGE_SMEM_BYTES (S_SIZE * 4)

__global__ __launch_bounds__(256, 3)
void edge_kernel(const float* __restrict__ x, const void* __restrict__ ei,
                 const float* __restrict__ edge_attr,
                 const float* __restrict__ We_w1, const float* __restrict__ Wx_w1,
                 const float* __restrict__ We_w2, const float* __restrict__ We_b2,
                 const float* __restrict__ Watt_w, const float* __restrict__ Watt_b,
                 const float* __restrict__ Wx_w2, const float* __restrict__ Wx_b2,
                 const float* __restrict__ Wx_w3)
{
    extern __shared__ float sm[];
    int tid = threadIdx.x;
    int e0 = blockIdx.x * ET;
    int is64 = g_is64;
    float attb = Watt_b[0];

    // ---- stage weights ----
    for (int i = tid; i < 2176; i += 256) sm[S_W1E + i] = We_w1[256 * 128 + i];
    for (int i = tid; i < 2048; i += 256) sm[S_W1X + i] = Wx_w1[256 * 128 + i];
    if (tid < 128) {
        sm[S_B2E + tid]  = We_b2[tid];
        sm[S_B2X + tid]  = Wx_b2[tid];
        sm[S_WATT + tid] = Watt_w[tid];
        sm[S_WX3 + tid]  = Wx_w3[tid];
    }

    int* sSrc = (int*)(sm + S_SRC);
    int* sDst = (int*)(sm + S_DST);

    // ---- stage per-edge scalars ----
    if (tid < ET) {
        int ge = e0 + tid;
        int s, d;
        if (is64) { const long long* p = (const long long*)ei; s = (int)p[ge]; d = (int)p[NE + ge]; }
        else      { const int* p = (const int*)ei;             s = p[ge];      d = p[NE + ge]; }
        sSrc[tid] = s; sDst[tid] = d;
        float dx = x[s * 3 + 0] - x[d * 3 + 0];
        float dy = x[s * 3 + 1] - x[d * 3 + 1];
        float dz = x[s * 3 + 2] - x[d * 3 + 2];
        float dsq = dx * dx + dy * dy + dz * dz;
        float inv = 1.f / (sqrtf(dsq + 1e-8f) + 1.f);
        sm[S_EXT + tid] = dsq;
        sm[S_DIFFN + 0 * 64 + tid] = dx * inv;
        sm[S_DIFFN + 1 * 64 + tid] = dy * inv;
        sm[S_DIFFN + 2 * 64 + tid] = dz * inv;
    }
    for (int idx = tid; idx < ET * EDD; idx += 256) {
        int j = idx >> 6, e = idx & 63;
        sm[S_EXT + (1 + j) * 64 + e] = edge_attr[(size_t)(e0 + e) * EDD + j];
    }
    __syncthreads();

    // thread mappings:
    //  GEMM: lane owns cols {c0,c0+1,c1,c1+1}; warp owns 8 edges (eg = warp id)
    //  phase A: elocal = lane>>2, chunk = lane&3; thread owns interleaved cols {16j + 4*chunk + t}
    int lane = tid & 31, eg = tid >> 5;
    int c0 = 2 * lane, c1 = 64 + c0;
    int elocal = lane >> 2, chunk = lane & 3;
    int eA = eg * 8 + elocal;

    // =================== PATH 1: phi_e / attention / msg ===================
    {
        int s = sSrc[eA], d = sDst[eA];
        const float* a1r = g_A1 + (size_t)s * HH + 4 * chunk;
        const float* a2r = g_A2 + (size_t)d * HH + 4 * chunk;
        u64 u[16];
#pragma unroll
        for (int j = 0; j < 8; j++) {
            ulonglong2 va = *(const ulonglong2*)(a1r + 16 * j);
            ulonglong2 vb = *(const ulonglong2*)(a2r + 16 * j);
            u[2 * j]     = f2add(va.x, vb.x);
            u[2 * j + 1] = f2add(va.y, vb.y);
        }
#pragma unroll 1
        for (int r = 0; r < 17; r++) {
            float ev = sm[S_EXT + r * 64 + eA];
            u64 ev2 = pk(ev, ev);
            const float* wr = sm + S_W1E + r * 128 + 4 * chunk;
#pragma unroll
            for (int j = 0; j < 8; j++) {
                ulonglong2 w = *(const ulonglong2*)(wr + 16 * j);
                u[2 * j]     = f2fma(ev2, w.x, u[2 * j]);
                u[2 * j + 1] = f2fma(ev2, w.y, u[2 * j + 1]);
            }
        }
#pragma unroll
        for (int j = 0; j < 8; j++) {
            int kb = 16 * j + 4 * chunk;
            float a, b;
            upk(a, b, u[2 * j]);
            sm[S_ACT + (kb + 0) * 64 + eA] = silu_f(a);
            sm[S_ACT + (kb + 1) * 64 + eA] = silu_f(b);
            upk(a, b, u[2 * j + 1]);
            sm[S_ACT + (kb + 2) * 64 + eA] = silu_f(a);
            sm[S_ACT + (kb + 3) * 64 + eA] = silu_f(b);
        }
    }
    __syncthreads();

    // ---- GEMM1: m2 = act @ We_w2 + b2 (4 cols x 8 edges per thread) ----
    u64 accA[4], accB[4], accC[4], accD[4];
    {
        float2 blo = *(const float2*)(sm + S_B2E + c0);
        float2 bhi = *(const float2*)(sm + S_B2E + c1);
        u64 pA = pk(blo.x, blo.x), pB = pk(blo.y, blo.y);
        u64 pC = pk(bhi.x, bhi.x), pD = pk(bhi.y, bhi.y);
#pragma unroll
        for (int j = 0; j < 4; j++) { accA[j] = pA; accB[j] = pB; accC[j] = pC; accD[j] = pD; }
    }
    {
        const float* abase = sm + S_ACT + eg * 8;
#pragma unroll 4
        for (int k = 0; k < 128; k++) {
            float2 wlo = __ldg((const float2*)(We_w2 + k * 128 + c0));
            float2 whi = __ldg((const float2*)(We_w2 + k * 128 + c1));
            u64 w00 = pk(wlo.x, wlo.x), w01 = pk(wlo.y, wlo.y);
            u64 w10 = pk(whi.x, whi.x), w11 = pk(whi.y, whi.y);
            const ulonglong2* mp = (const ulonglong2*)(abase + k * 64);
            ulonglong2 ma = mp[0];
            accA[0] = f2fma(ma.x, w00, accA[0]); accB[0] = f2fma(ma.x, w01, accB[0]);
            accC[0] = f2fma(ma.x, w10, accC[0]); accD[0] = f2fma(ma.x, w11, accD[0]);
            accA[1] = f2fma(ma.y, w00, accA[1]); accB[1] = f2fma(ma.y, w01, accB[1]);
            accC[1] = f2fma(ma.y, w10, accC[1]); accD[1] = f2fma(ma.y, w11, accD[1]);
            ulonglong2 mb = mp[1];
            accA[2] = f2fma(mb.x, w00, accA[2]); accB[2] = f2fma(mb.x, w01, accB[2]);
            accC[2] = f2fma(mb.x, w10, accC[2]); accD[2] = f2fma(mb.x, w11, accD[2]);
            accA[3] = f2fma(mb.y, w00, accA[3]); accB[3] = f2fma(mb.y, w01, accB[3]);
            accC[3] = f2fma(mb.y, w10, accC[3]); accD[3] = f2fma(mb.y, w11, accD[3]);
        }
    }

    // ---- attention: per-edge sum over ALL 128 cols, fully in-warp ----
    float att[8];
    {
        float2 walo = *(const float2*)(sm + S_WATT + c0);
        float2 wahi = *(const float2*)(sm + S_WATT + c1);
        u64 pw0 = pk(walo.x, walo.x), pw1 = pk(walo.y, walo.y);
        u64 pw2 = pk(wahi.x, wahi.x), pw3 = pk(wahi.y, wahi.y);
        u64 z = pk(0.f, 0.f);
        u64 pa[4];
#pragma unroll
        for (int j = 0; j < 4; j++)
            pa[j] = f2fma(accA[j], pw0, f2fma(accB[j], pw1,
                    f2fma(accC[j], pw2, f2fma(accD[j], pw3, z))));
#pragma unroll
        for (int msk = 16; msk > 0; msk >>= 1)
#pragma unroll
            for (int j = 0; j < 4; j++)
                pa[j] = f2add(pa[j], __shfl_xor_sync(0xffffffffu, pa[j], msk));
#pragma unroll
        for (int j = 0; j < 4; j++) {
            float s0, s1; upk(s0, s1, pa[j]);
            att[2 * j]     = 1.f / (1.f + __expf(-(s0 + attb)));
            att[2 * j + 1] = 1.f / (1.f + __expf(-(s1 + attb)));
        }
    }

    // ---- msg scatter: coalesced per-warp ----
    {
        float me0[8], me1[8], me2[8], me3[8];
#pragma unroll
        for (int j = 0; j < 4; j++) {
            upk(me0[2 * j], me0[2 * j + 1], accA[j]);
            upk(me1[2 * j], me1[2 * j + 1], accB[j]);
            upk(me2[2 * j], me2[2 * j + 1], accC[j]);
            upk(me3[2 * j], me3[2 * j + 1], accD[j]);
        }
#pragma unroll
        for (int e = 0; e < 8; e++) {
            int d = sDst[eg * 8 + e];
            float ae = att[e];
            float* row = g_msg + (size_t)d * HH;
            red2(row + c0, ae * me0[e], ae * me1[e]);
            red2(row + c1, ae * me2[e], ae * me3[e]);
        }
    }
    __syncthreads();

    // =================== PATH 2: phi_x / coord ===================
    {
        int s = sSrc[eA], d = sDst[eA];
        const float* b1r = g_B1 + (size_t)s * HH + 4 * chunk;
        const float* b2r = g_B2 + (size_t)d * HH + 4 * chunk;
        u64 u[16];
#pragma unroll
        for (int j = 0; j < 8; j++) {
            ulonglong2 va = *(const ulonglong2*)(b1r + 16 * j);
            ulonglong2 vb = *(const ulonglong2*)(b2r + 16 * j);
            u[2 * j]     = f2add(va.x, vb.x);
            u[2 * j + 1] = f2add(va.y, vb.y);
        }
#pragma unroll 1
        for (int r = 0; r < 16; r++) {
            float ev = sm[S_EXT + (1 + r) * 64 + eA];
            u64 ev2 = pk(ev, ev);
            const float* wr = sm + S_W1X + r * 128 + 4 * chunk;
#pragma unroll
            for (int j = 0; j < 8; j++) {
                ulonglong2 w = *(const ulonglong2*)(wr + 16 * j);
                u[2 * j]     = f2fma(ev2, w.x, u[2 * j]);
                u[2 * j + 1] = f2fma(ev2, w.y, u[2 * j + 1]);
            }
        }
#pragma unroll
        for (int j = 0; j < 8; j++) {
            int kb = 16 * j + 4 * chunk;
            float a, b;
            upk(a, b, u[2 * j]);
            sm[S_ACT + (kb + 0) * 64 + eA] = silu_f(a);
            sm[S_ACT + (kb + 1) * 64 + eA] = silu_f(b);
            upk(a, b, u[2 * j + 1]);
            sm[S_ACT + (kb + 2) * 64 + eA] = silu_f(a);
            sm[S_ACT + (kb + 3) * 64 + eA] = silu_f(b);
        }
    }
    __syncthreads();

    // ---- GEMM2: c2 = act @ Wx_w2 + b2x ----
    {
        float2 blo = *(const float2*)(sm + S_B2X + c0);
        float2 bhi = *(const float2*)(sm + S_B2X + c1);
        u64 pA = pk(blo.x, blo.x), pB = pk(blo.y, blo.y);
        u64 pC = pk(bhi.x, bhi.x), pD = pk(bhi.y, bhi.y);
#pragma unroll
        for (int j = 0; j < 4; j++) { accA[j] = pA; accB[j] = pB; accC[j] = pC; accD[j] = pD; }
    }
    {
        const float* abase = sm + S_ACT + eg * 8;
#pragma unroll 4
        for (int k = 0; k < 128; k++) {
            float2 wlo = __ldg((const float2*)(Wx_w2 + k * 128 + c0));
            float2 whi = __ldg((const float2*)(Wx_w2 + k * 128 + c1));
            u64 w00 = pk(wlo.x, wlo.x), w01 = pk(wlo.y, wlo.y);
            u64 w10 = pk(whi.x, whi.x), w11 = pk(whi.y, whi.y);
            const ulonglong2* mp = (const ulonglong2*)(abase + k * 64);
            ulonglong2 ma = mp[0];
            accA[0] = f2fma(ma.x, w00, accA[0]); accB[0] = f2fma(ma.x, w01, accB[0]);
            accC[0] = f2fma(ma.x, w10, accC[0]); accD[0] = f2fma(ma.x, w11, accD[0]);
            accA[1] = f2fma(ma.y, w00, accA[1]); accB[1] = f2fma(ma.y, w01, accB[1]);
            accC[1] = f2fma(ma.y, w10, accC[1]); accD[1] = f2fma(ma.y, w11, accD[1]);
            ulonglong2 mb = mp[1];
            accA[2] = f2fma(mb.x, w00, accA[2]); accB[2] = f2fma(mb.x, w01, accB[2]);
            accC[2] = f2fma(mb.x, w10, accC[2]); accD[2] = f2fma(mb.x, w11, accD[2]);
            accA[3] = f2fma(mb.y, w00, accA[3]); accB[3] = f2fma(mb.y, w01, accB[3]);
            accC[3] = f2fma(mb.y, w10, accC[3]); accD[3] = f2fma(mb.y, w11, accD[3]);
        }
    }

    // ---- coord weight + scatter ----
    {
        float2 w3lo = *(const float2*)(sm + S_WX3 + c0);
        float2 w3hi = *(const float2*)(sm + S_WX3 + c1);
        u64 pc[4];
#pragma unroll
        for (int j = 0; j < 4; j++) {
            float a, b, plo, phi;
            upk(a, b, accA[j]); plo  = silu_f(a) * w3lo.x; phi  = silu_f(b) * w3lo.x;
            upk(a, b, accB[j]); plo += silu_f(a) * w3lo.y; phi += silu_f(b) * w3lo.y;
            upk(a, b, accC[j]); plo += silu_f(a) * w3hi.x; phi += silu_f(b) * w3hi.x;
            upk(a, b, accD[j]); plo += silu_f(a) * w3hi.y; phi += silu_f(b) * w3hi.y;
            pc[j] = pk(plo, phi);
        }
#pragma unroll
        for (int msk = 16; msk > 0; msk >>= 1)
#pragma unroll
            for (int j = 0; j < 4; j++)
                pc[j] = f2add(pc[j], __shfl_xor_sync(0xffffffffu, pc[j], msk));
        if (lane < 8) {
            int el = eg * 8 + lane;
            float s0, s1; upk(s0, s1, pc[lane >> 1]);
            float s = (lane & 1) ? s1 : s0;
            float cw = tanhf(s) * 2.5f;
            int d = sDst[el];
            atomicAdd(&g_coord[d * 3 + 0], sm[S_DIFFN + 0 * 64 + el] * cw);
            atomicAdd(&g_coord[d * 3 + 1], sm[S_DIFFN + 1 * 64 + el] * cw);
            atomicAdd(&g_coord[d * 3 + 2], sm[S_DIFFN + 2 * 64 + el] * cw);
        }
    }
}

// ---------------- phi_h + output assembly (streaming, batched L2 weight loads) ----------------
#define N_INT   0                      // sInT: 256 x NBP
#define N_HID   (N_INT + 256*NBP)      // sHidT: 128 x NBP
#define NODE_SMEM_FLOATS (N_HID + 128*NBP)
#define NODE_SMEM_BYTES  (NODE_SMEM_FLOATS * 4)

__global__ __launch_bounds__(256, 4)
void node_out_kernel(const float* __restrict__ h, const float* __restrict__ x,
                     const float* __restrict__ Wh_w1, const float* __restrict__ Wh_b1,
                     const float* __restrict__ Wh_w2, const float* __restrict__ Wh_b2,
                     float* __restrict__ out)
{
    extern __shared__ float sm[];
    int tid = threadIdx.x;
    int n0 = blockIdx.x * NB;

    {
        int k = tid;
#pragma unroll 4
        for (int j = 0; j < NB; j++) {
            int n = n0 + j;
            float v = 0.f;
            if (n < NN) {
                v = (k < 128) ? h[(size_t)n * HH + k]
                              : g_msg[(size_t)n * HH + (k - 128)];
            }
            sm[N_INT + k * NBP + j] = v;
        }
    }
    __syncthreads();

    int cidx = tid & 63, grp = tid >> 6;
    int c0 = 2 * cidx, jb = grp * 8;

    u64 acc0[4], acc1[4];
    {
        float2 bb = __ldg((const float2*)(Wh_b1 + c0));
        u64 p0 = pk(bb.x, bb.x), p1 = pk(bb.y, bb.y);
#pragma unroll
        for (int q = 0; q < 4; q++) { acc0[q] = p0; acc1[q] = p1; }
    }
    {
        const float2* wbase = (const float2*)(Wh_w1 + c0);
        const float* mbase = sm + N_INT + jb;
        for (int k0 = 0; k0 < 256; k0 += 4) {
            float2 w0 = __ldg(wbase + (k0 + 0) * 64);
            float2 w1 = __ldg(wbase + (k0 + 1) * 64);
            float2 w2 = __ldg(wbase + (k0 + 2) * 64);
            float2 w3 = __ldg(wbase + (k0 + 3) * 64);
            float2 wk[4] = {w0, w1, w2, w3};
#pragma unroll
            for (int i = 0; i < 4; i++) {
                u64 ww0 = pk(wk[i].x, wk[i].x), ww1 = pk(wk[i].y, wk[i].y);
                const ulonglong2* mp = (const ulonglong2*)(mbase + (k0 + i) * NBP);
                ulonglong2 m0 = mp[0];
                acc0[0] = f2fma(m0.x, ww0, acc0[0]); acc1[0] = f2fma(m0.x, ww1, acc1[0]);
                acc0[1] = f2fma(m0.y, ww0, acc0[1]); acc1[1] = f2fma(m0.y, ww1, acc1[1]);
                ulonglong2 m1 = mp[1];
                acc0[2] = f2fma(m1.x, ww0, acc0[2]); acc1[2] = f2fma(m1.x, ww1, acc1[2]);
                acc0[3] = f2fma(m1.y, ww0, acc0[3]); acc1[3] = f2fma(m1.y, ww1, acc1[3]);
            }
        }
    }
#pragma unroll
    for (int q = 0; q < 4; q++) {
        float a, b;
        upk(a, b, acc0[q]);
        *(u64*)(sm + N_HID + c0 * NBP + jb + 2 * q) = pk(silu_f(a), silu_f(b));
        upk(a, b, acc1[q]);
        *(u64*)(sm + N_HID + (c0 + 1) * NBP + jb + 2 * q) = pk(silu_f(a), silu_f(b));
    }
    __syncthreads();

    u64 acc2[4], acc3[4];
    {
        float2 bb = __ldg((const float2*)(Wh_b2 + c0));
        u64 p0 = pk(bb.x, bb.x), p1 = pk(bb.y, bb.y);
#pragma unroll
        for (int q = 0; q < 4; q++) { acc2[q] = p0; acc3[q] = p1; }
    }
    {
        const float2* wbase = (const float2*)(Wh_w2 + c0);
        const float* mbase = sm + N_HID + jb;
        for (int k0 = 0; k0 < 128; k0 += 4) {
            float2 w0 = __ldg(wbase + (k0 + 0) * 64);
            float2 w1 = __ldg(wbase + (k0 + 1) * 64);
            float2 w2 = __ldg(wbase + (k0 + 2) * 64);
            float2 w3 = __ldg(wbase + (k0 + 3) * 64);
            float2 wk[4] = {w0, w1, w2, w3};
#pragma unroll
            for (int i = 0; i < 4; i++) {
                u64 ww0 = pk(wk[i].x, wk[i].x), ww1 = pk(wk[i].y, wk[i].y);
                const ulonglong2* mp = (const ulonglong2*)(mbase + (k0 + i) * NBP);
                ulonglong2 m0 = mp[0];
                acc2[0] = f2fma(m0.x, ww0, acc2[0]); acc3[0] = f2fma(m0.x, ww1, acc3[0]);
                acc2[1] = f2fma(m0.y, ww0, acc2[1]); acc3[1] = f2fma(m0.y, ww1, acc3[1]);
                ulonglong2 m1 = mp[1];
                acc2[2] = f2fma(m1.x, ww0, acc2[2]); acc3[2] = f2fma(m1.x, ww1, acc3[2]);
                acc2[3] = f2fma(m1.y, ww0, acc2[3]); acc3[3] = f2fma(m1.y, ww1, acc3[3]);
            }
        }
    }
#pragma unroll
    for (int q = 0; q < 4; q++) {
        float a0, b0, a1, b1;
        upk(a0, b0, acc2[q]);
        upk(a1, b1, acc3[q]);
        int na = n0 + jb + 2 * q, nb2 = na + 1;
        if (na < NN) {
            float2 hv = *(const float2*)(h + (size_t)na * HH + c0);
            *(float2*)(out + (size_t)na * HH + c0) = make_float2(hv.x + a0, hv.y + a1);
        }
        if (nb2 < NN) {
            float2 hv = *(const float2*)(h + (size_t)nb2 * HH + c0);
            *(float2*)(out + (size_t)nb2 * HH + c0) = make_float2(hv.x + b0, hv.y + b1);
        }
    }
    if (tid < NB * 3) {
        int n = n0 + tid / 3, c = tid % 3;
        if (n < NN)
            out[(size_t)NN * HH + n * 3 + c] = x[n * 3 + c] + g_coord[n * 3 + c];
    }
}

// ---------------- launch ----------------
extern "C" void kernel_launch(void* const* d_in, const int* in_sizes, int n_in,
                              void* d_out, int out_size) {
    const float* h         = (const float*)d_in[0];
    const float* x         = (const float*)d_in[1];
    const void*  ei        = d_in[2];
    const float* edge_attr = (const float*)d_in[3];
    const float* t_emb     = (const float*)d_in[4];
    const float* We_w1     = (const float*)d_in[5];
    const float* We_b1     = (const float*)d_in[6];
    const float* We_w2     = (const float*)d_in[7];
    const float* We_b2     = (const float*)d_in[8];
    const float* Watt_w    = (const float*)d_in[9];
    const float* Watt_b    = (const float*)d_in[10];
    const float* Wx_w1     = (const float*)d_in[11];
    const float* Wx_b1     = (const float*)d_in[12];
    const float* Wx_w2     = (const float*)d_in[13];
    const float* Wx_b2     = (const float*)d_in[14];
    const float* Wx_w3     = (const float*)d_in[15];
    const float* Wh_w1     = (const float*)d_in[16];
    const float* Wh_b1     = (const float*)d_in[17];
    const float* Wh_w2     = (const float*)d_in[18];
    const float* Wh_b2     = (const float*)d_in[19];
    float* out = (float*)d_out;

    cudaFuncSetAttribute(edge_kernel, cudaFuncAttributeMaxDynamicSharedMemorySize, EDGE_SMEM_BYTES);
    cudaFuncSetAttribute(node_out_kernel, cudaFuncAttributeMaxDynamicSharedMemorySize, NODE_SMEM_BYTES);

    int eblocks = NE / ET;
    int nblocks = (NN + NB - 1) / NB;

    precompute_kernel<<<NN / PC_NB, 128>>>(h, t_emb, We_w1, We_b1, Wx_w1, Wx_b1, ei);
    edge_kernel<<<eblocks, 256, EDGE_SMEM_BYTES>>>(x, ei, edge_attr, We_w1, Wx_w1,
                                                   We_w2, We_b2, Watt_w, Watt_b,
                                                   Wx_w2, Wx_b2, Wx_w3);
    node_out_kernel<<<nblocks, 256, NODE_SMEM_BYTES>>>(h, x, Wh_w1, Wh_b1, Wh_w2, Wh_b2, out);
}

// round 17
// speedup vs baseline: 1.5740x; 1.5740x over previous
#include <cuda_runtime.h>
#include <math.h>

#define NN 50000
#define NE 600000
#define HH 128
#define EDD 16
#define TDD 32

#define ET 64      // edges per block (edge kernel)
#define PC_NB 8
#define NB 32      // nodes per block (node_out)
#define NBP 36     // padded stride

static_assert(NN % PC_NB == 0, "precompute exact");
static_assert(NE % ET == 0, "edge tile exact");

// ---------------- device scratch ----------------
__device__ float g_A1[NN * HH];
__device__ float g_A2[NN * HH];
__device__ float g_B1[NN * HH];
__device__ float g_B2[NN * HH];
__device__ float g_msg[NN * HH];
__device__ float g_coord[NN * 3];
__device__ int   g_is64;

typedef unsigned long long u64;

__device__ __forceinline__ u64 pk(float lo, float hi) {
    u64 r; asm("mov.b64 %0,{%1,%2};" : "=l"(r) : "f"(lo), "f"(hi)); return r;
}
__device__ __forceinline__ void upk(float& lo, float& hi, u64 v) {
    asm("mov.b64 {%0,%1},%2;" : "=f"(lo), "=f"(hi) : "l"(v));
}
__device__ __forceinline__ u64 f2fma(u64 a, u64 b, u64 c) {
    u64 d; asm("fma.rn.f32x2 %0,%1,%2,%3;" : "=l"(d) : "l"(a), "l"(b), "l"(c)); return d;
}
__device__ __forceinline__ u64 f2add(u64 a, u64 b) {
    u64 d; asm("add.rn.f32x2 %0,%1,%2;" : "=l"(d) : "l"(a), "l"(b)); return d;
}
__device__ __forceinline__ void red2(float* addr, float a, float b) {
    asm volatile("red.global.add.v2.f32 [%0], {%1,%2};" :: "l"(addr), "f"(a), "f"(b) : "memory");
}
__device__ __forceinline__ float silu_f(float v) {
    return v / (1.f + __expf(-v));
}

// ---------------- int32 vs int64 edge_index detection ----------------
__global__ void detect_kernel(const void* __restrict__ ei) {
    __shared__ int ok;
    if (threadIdx.x == 0) ok = 1;
    __syncthreads();
    const long long* p = (const long long*)ei;
    long long v = p[threadIdx.x];
    if (v < 0 || v >= NN) atomicExch(&ok, 0);
    __syncthreads();
    if (threadIdx.x == 0) g_is64 = ok;
}

// ---------------- per-node layer-1 partials (f32x2) ----------------
__global__ __launch_bounds__(128)
void precompute_kernel(const float* __restrict__ h, const float* __restrict__ t_emb,
                       const float* __restrict__ We_w1, const float* __restrict__ We_b1,
                       const float* __restrict__ Wx_w1, const float* __restrict__ Wx_b1)
{
    __shared__ float hbufT[HH * PC_NB];
    __shared__ float tbufT[TDD * PC_NB];
    int col = threadIdx.x;
    int n0 = blockIdx.x * PC_NB;

    for (int i = col; i < PC_NB * HH; i += 128) {
        int j = i >> 7, k = i & 127;
        hbufT[k * PC_NB + j] = h[(size_t)(n0 + j) * HH + k];
    }
    for (int i = col; i < PC_NB * TDD; i += 128) {
        int j = i >> 5, k = i & 31;
        tbufT[k * PC_NB + j] = t_emb[(size_t)(n0 + j) * TDD + k];
    }
    __syncthreads();

    u64 a1[4], a2[4], b1[4], b2[4];
    {
        float be = We_b1[col], bx = Wx_b1[col];
        u64 pbe = pk(be, be), pbx = pk(bx, bx), z = pk(0.f, 0.f);
#pragma unroll
        for (int j = 0; j < 4; j++) { a1[j] = pbe; b1[j] = pbx; a2[j] = z; b2[j] = z; }
    }
#pragma unroll 4
    for (int k = 0; k < HH; k++) {
        float wa1 = We_w1[(size_t)k * HH + col];
        float wa2 = We_w1[(size_t)(HH + k) * HH + col];
        float wb1 = Wx_w1[(size_t)k * HH + col];
        float wb2 = Wx_w1[(size_t)(HH + k) * HH + col];
        u64 pa1 = pk(wa1, wa1), pa2 = pk(wa2, wa2);
        u64 pb1 = pk(wb1, wb1), pb2 = pk(wb2, wb2);
        const u64* ph = (const u64*)(hbufT + k * PC_NB);
#pragma unroll
        for (int j = 0; j < 4; j++) {
            u64 hv = ph[j];
            a1[j] = f2fma(hv, pa1, a1[j]);
            a2[j] = f2fma(hv, pa2, a2[j]);
            b1[j] = f2fma(hv, pb1, b1[j]);
            b2[j] = f2fma(hv, pb2, b2[j]);
        }
    }
#pragma unroll 4
    for (int k = 0; k < TDD; k++) {
        float wta = We_w1[(size_t)(273 + k) * HH + col];
        float wtb = Wx_w1[(size_t)(272 + k) * HH + col];
        u64 pta = pk(wta, wta), ptb = pk(wtb, wtb);
        const u64* pt = (const u64*)(tbufT + k * PC_NB);
#pragma unroll
        for (int j = 0; j < 4; j++) {
            u64 tv = pt[j];
            a1[j] = f2fma(tv, pta, a1[j]);
            b1[j] = f2fma(tv, ptb, b1[j]);
        }
    }
#pragma unroll
    for (int j = 0; j < 4; j++) {
        size_t o0 = (size_t)(n0 + 2 * j) * HH + col;
        size_t o1 = o0 + HH;
        float x0, x1;
        upk(x0, x1, a1[j]); g_A1[o0] = x0; g_A1[o1] = x1;
        upk(x0, x1, a2[j]); g_A2[o0] = x0; g_A2[o1] = x1;
        upk(x0, x1, b1[j]); g_B1[o0] = x0; g_B1[o1] = x1;
        upk(x0, x1, b2[j]); g_B2[o0] = x0; g_B2[o1] = x1;
        g_msg[o0] = 0.f; g_msg[o1] = 0.f;
    }
    if (col < PC_NB * 3) g_coord[n0 * 3 + col] = 0.f;
}

// ================= merged edge kernel =================
// smem float offsets
#define S_W1E   0                    // 17 x 128 (We_w1 rows 256..272)
#define S_W1X   (S_W1E + 2176)       // 16 x 128 (Wx_w1 rows 256..271)
#define S_B2E   (S_W1X + 2048)       // 128
#define S_B2X   (S_B2E + 128)
#define S_WATT  (S_B2X + 128)
#define S_WX3   (S_WATT + 128)
#define S_EXT   (S_WX3 + 128)        // 17 x 64 [row][edge]; row0=dsq, rows1..16=edge_attr
#define S_DIFFN (S_EXT + 17*64)      // 3 x 64
#define S_SRC   (S_DIFFN + 192)      // 64 ints
#define S_DST   (S_SRC + 64)
#define S_ACT   (S_DST + 64)         // 128 x 64 [k][edge], reused for both paths
#define S_SIZE  (S_ACT + 128*64)
#define EDGE_SMEM_BYTES (S_SIZE * 4)

__global__ __launch_bounds__(256, 3)
void edge_kernel(const float* __restrict__ x, const void* __restrict__ ei,
                 const float* __restrict__ edge_attr,
                 const float* __restrict__ We_w1, const float* __restrict__ Wx_w1,
                 const float* __restrict__ We_w2, const float* __restrict__ We_b2,
                 const float* __restrict__ Watt_w, const float* __restrict__ Watt_b,
                 const float* __restrict__ Wx_w2, const float* __restrict__ Wx_b2,
                 const float* __restrict__ Wx_w3)
{
    extern __shared__ float sm[];
    int tid = threadIdx.x;
    int e0 = blockIdx.x * ET;
    int is64 = g_is64;
    float attb = Watt_b[0];

    // ---- stage weights ----
    for (int i = tid; i < 2176; i += 256) sm[S_W1E + i] = We_w1[256 * 128 + i];
    for (int i = tid; i < 2048; i += 256) sm[S_W1X + i] = Wx_w1[256 * 128 + i];
    if (tid < 128) {
        sm[S_B2E + tid]  = We_b2[tid];
        sm[S_B2X + tid]  = Wx_b2[tid];
        sm[S_WATT + tid] = Watt_w[tid];
        sm[S_WX3 + tid]  = Wx_w3[tid];
    }

    int* sSrc = (int*)(sm + S_SRC);
    int* sDst = (int*)(sm + S_DST);

    // ---- stage per-edge scalars ----
    if (tid < ET) {
        int ge = e0 + tid;
        int s, d;
        if (is64) { const long long* p = (const long long*)ei; s = (int)p[ge]; d = (int)p[NE + ge]; }
        else      { const int* p = (const int*)ei;             s = p[ge];      d = p[NE + ge]; }
        sSrc[tid] = s; sDst[tid] = d;
        float dx = x[s * 3 + 0] - x[d * 3 + 0];
        float dy = x[s * 3 + 1] - x[d * 3 + 1];
        float dz = x[s * 3 + 2] - x[d * 3 + 2];
        float dsq = dx * dx + dy * dy + dz * dz;
        float inv = 1.f / (sqrtf(dsq + 1e-8f) + 1.f);
        sm[S_EXT + tid] = dsq;
        sm[S_DIFFN + 0 * 64 + tid] = dx * inv;
        sm[S_DIFFN + 1 * 64 + tid] = dy * inv;
        sm[S_DIFFN + 2 * 64 + tid] = dz * inv;
    }
    for (int idx = tid; idx < ET * EDD; idx += 256) {
        int j = idx >> 6, e = idx & 63;
        sm[S_EXT + (1 + j) * 64 + e] = edge_attr[(size_t)(e0 + e) * EDD + j];
    }
    __syncthreads();

    // thread mappings:
    //  GEMM: lane owns cols {c0,c0+1,c1,c1+1}; warp owns 8 edges (eg = warp id)
    //  phase A: elocal = lane>>2, chunk = lane&3; thread owns interleaved cols {16j + 4*chunk + t}
    int lane = tid & 31, eg = tid >> 5;
    int c0 = 2 * lane, c1 = 64 + c0;
    int elocal = lane >> 2, chunk = lane & 3;
    int eA = eg * 8 + elocal;

    // =================== PATH 1: phi_e / attention / msg ===================
    {
        int s = sSrc[eA], d = sDst[eA];
        const float* a1r = g_A1 + (size_t)s * HH + 4 * chunk;
        const float* a2r = g_A2 + (size_t)d * HH + 4 * chunk;
        u64 u[16];
#pragma unroll
        for (int j = 0; j < 8; j++) {
            ulonglong2 va = *(const ulonglong2*)(a1r + 16 * j);
            ulonglong2 vb = *(const ulonglong2*)(a2r + 16 * j);
            u[2 * j]     = f2add(va.x, vb.x);
            u[2 * j + 1] = f2add(va.y, vb.y);
        }
#pragma unroll 1
        for (int r = 0; r < 17; r++) {
            float ev = sm[S_EXT + r * 64 + eA];
            u64 ev2 = pk(ev, ev);
            const float* wr = sm + S_W1E + r * 128 + 4 * chunk;
#pragma unroll
            for (int j = 0; j < 8; j++) {
                ulonglong2 w = *(const ulonglong2*)(wr + 16 * j);
                u[2 * j]     = f2fma(ev2, w.x, u[2 * j]);
                u[2 * j + 1] = f2fma(ev2, w.y, u[2 * j + 1]);
            }
        }
#pragma unroll
        for (int j = 0; j < 8; j++) {
            int kb = 16 * j + 4 * chunk;
            float a, b;
            upk(a, b, u[2 * j]);
            sm[S_ACT + (kb + 0) * 64 + eA] = silu_f(a);
            sm[S_ACT + (kb + 1) * 64 + eA] = silu_f(b);
            upk(a, b, u[2 * j + 1]);
            sm[S_ACT + (kb + 2) * 64 + eA] = silu_f(a);
            sm[S_ACT + (kb + 3) * 64 + eA] = silu_f(b);
        }
    }
    __syncthreads();

    // ---- GEMM1: m2 = act @ We_w2 + b2 ----
    u64 accA[4], accB[4], accC[4], accD[4];
    {
        float2 blo = *(const float2*)(sm + S_B2E + c0);
        float2 bhi = *(const float2*)(sm + S_B2E + c1);
        u64 pA = pk(blo.x, blo.x), pB = pk(blo.y, blo.y);
        u64 pC = pk(bhi.x, bhi.x), pD = pk(bhi.y, bhi.y);
#pragma unroll
        for (int j = 0; j < 4; j++) { accA[j] = pA; accB[j] = pB; accC[j] = pC; accD[j] = pD; }
    }
    {
        const float* abase = sm + S_ACT + eg * 8;
#pragma unroll 4
        for (int k = 0; k < 128; k++) {
            float2 wlo = __ldg((const float2*)(We_w2 + k * 128 + c0));
            float2 whi = __ldg((const float2*)(We_w2 + k * 128 + c1));
            u64 w00 = pk(wlo.x, wlo.x), w01 = pk(wlo.y, wlo.y);
            u64 w10 = pk(whi.x, whi.x), w11 = pk(whi.y, whi.y);
            const ulonglong2* mp = (const ulonglong2*)(abase + k * 64);
            ulonglong2 ma = mp[0];
            accA[0] = f2fma(ma.x, w00, accA[0]); accB[0] = f2fma(ma.x, w01, accB[0]);
            accC[0] = f2fma(ma.x, w10, accC[0]); accD[0] = f2fma(ma.x, w11, accD[0]);
            accA[1] = f2fma(ma.y, w00, accA[1]); accB[1] = f2fma(ma.y, w01, accB[1]);
            accC[1] = f2fma(ma.y, w10, accC[1]); accD[1] = f2fma(ma.y, w11, accD[1]);
            ulonglong2 mb = mp[1];
            accA[2] = f2fma(mb.x, w00, accA[2]); accB[2] = f2fma(mb.x, w01, accB[2]);
            accC[2] = f2fma(mb.x, w10, accC[2]); accD[2] = f2fma(mb.x, w11, accD[2]);
            accA[3] = f2fma(mb.y, w00, accA[3]); accB[3] = f2fma(mb.y, w01, accB[3]);
            accC[3] = f2fma(mb.y, w10, accC[3]); accD[3] = f2fma(mb.y, w11, accD[3]);
        }
    }

    // ---- attention: per-edge sum over ALL 128 cols, fully in-warp ----
    float att[8];
    {
        float2 walo = *(const float2*)(sm + S_WATT + c0);
        float2 wahi = *(const float2*)(sm + S_WATT + c1);
        u64 pw0 = pk(walo.x, walo.x), pw1 = pk(walo.y, walo.y);
        u64 pw2 = pk(wahi.x, wahi.x), pw3 = pk(wahi.y, wahi.y);
        u64 z = pk(0.f, 0.f);
        u64 pa[4];
#pragma unroll
        for (int j = 0; j < 4; j++)
            pa[j] = f2fma(accA[j], pw0, f2fma(accB[j], pw1,
                    f2fma(accC[j], pw2, f2fma(accD[j], pw3, z))));
#pragma unroll
        for (int msk = 16; msk > 0; msk >>= 1)
#pragma unroll
            for (int j = 0; j < 4; j++)
                pa[j] = f2add(pa[j], __shfl_xor_sync(0xffffffffu, pa[j], msk));
#pragma unroll
        for (int j = 0; j < 4; j++) {
            float s0, s1; upk(s0, s1, pa[j]);
            att[2 * j]     = 1.f / (1.f + __expf(-(s0 + attb)));
            att[2 * j + 1] = 1.f / (1.f + __expf(-(s1 + attb)));
        }
    }

    // ---- msg scatter: coalesced per-warp ----
    {
        float me0[8], me1[8], me2[8], me3[8];
#pragma unroll
        for (int j = 0; j < 4; j++) {
            upk(me0[2 * j], me0[2 * j + 1], accA[j]);
            upk(me1[2 * j], me1[2 * j + 1], accB[j]);
            upk(me2[2 * j], me2[2 * j + 1], accC[j]);
            upk(me3[2 * j], me3[2 * j + 1], accD[j]);
        }
#pragma unroll
        for (int e = 0; e < 8; e++) {
            int d = sDst[eg * 8 + e];
            float ae = att[e];
            float* row = g_msg + (size_t)d * HH;
            red2(row + c0, ae * me0[e], ae * me1[e]);
            red2(row + c1, ae * me2[e], ae * me3[e]);
        }
    }
    __syncthreads();

    // =================== PATH 2: phi_x / coord ===================
    {
        int s = sSrc[eA], d = sDst[eA];
        const float* b1r = g_B1 + (size_t)s * HH + 4 * chunk;
        const float* b2r = g_B2 + (size_t)d * HH + 4 * chunk;
        u64 u[16];
#pragma unroll
        for (int j = 0; j < 8; j++) {
            ulonglong2 va = *(const ulonglong2*)(b1r + 16 * j);
            ulonglong2 vb = *(const ulonglong2*)(b2r + 16 * j);
            u[2 * j]     = f2add(va.x, vb.x);
            u[2 * j + 1] = f2add(va.y, vb.y);
        }
#pragma unroll 1
        for (int r = 0; r < 16; r++) {
            float ev = sm[S_EXT + (1 + r) * 64 + eA];
            u64 ev2 = pk(ev, ev);
            const float* wr = sm + S_W1X + r * 128 + 4 * chunk;
#pragma unroll
            for (int j = 0; j < 8; j++) {
                ulonglong2 w = *(const ulonglong2*)(wr + 16 * j);
                u[2 * j]     = f2fma(ev2, w.x, u[2 * j]);
                u[2 * j + 1] = f2fma(ev2, w.y, u[2 * j + 1]);
            }
        }
#pragma unroll
        for (int j = 0; j < 8; j++) {
            int kb = 16 * j + 4 * chunk;
            float a, b;
            upk(a, b, u[2 * j]);
            sm[S_ACT + (kb + 0) * 64 + eA] = silu_f(a);
            sm[S_ACT + (kb + 1) * 64 + eA] = silu_f(b);
            upk(a, b, u[2 * j + 1]);
            sm[S_ACT + (kb + 2) * 64 + eA] = silu_f(a);
            sm[S_ACT + (kb + 3) * 64 + eA] = silu_f(b);
        }
    }
    __syncthreads();

    // ---- GEMM2: c2 = act @ Wx_w2 + b2x ----
    {
        float2 blo = *(const float2*)(sm + S_B2X + c0);
        float2 bhi = *(const float2*)(sm + S_B2X + c1);
        u64 pA = pk(blo.x, blo.x), pB = pk(blo.y, blo.y);
        u64 pC = pk(bhi.x, bhi.x), pD = pk(bhi.y, bhi.y);
#pragma unroll
        for (int j = 0; j < 4; j++) { accA[j] = pA; accB[j] = pB; accC[j] = pC; accD[j] = pD; }
    }
    {
        const float* abase = sm + S_ACT + eg * 8;
#pragma unroll 4
        for (int k = 0; k < 128; k++) {
            float2 wlo = __ldg((const float2*)(Wx_w2 + k * 128 + c0));
            float2 whi = __ldg((const float2*)(Wx_w2 + k * 128 + c1));
            u64 w00 = pk(wlo.x, wlo.x), w01 = pk(wlo.y, wlo.y);
            u64 w10 = pk(whi.x, whi.x), w11 = pk(whi.y, whi.y);
            const ulonglong2* mp = (const ulonglong2*)(abase + k * 64);
            ulonglong2 ma = mp[0];
            accA[0] = f2fma(ma.x, w00, accA[0]); accB[0] = f2fma(ma.x, w01, accB[0]);
            accC[0] = f2fma(ma.x, w10, accC[0]); accD[0] = f2fma(ma.x, w11, accD[0]);
            accA[1] = f2fma(ma.y, w00, accA[1]); accB[1] = f2fma(ma.y, w01, accB[1]);
            accC[1] = f2fma(ma.y, w10, accC[1]); accD[1] = f2fma(ma.y, w11, accD[1]);
            ulonglong2 mb = mp[1];
            accA[2] = f2fma(mb.x, w00, accA[2]); accB[2] = f2fma(mb.x, w01, accB[2]);
            accC[2] = f2fma(mb.x, w10, accC[2]); accD[2] = f2fma(mb.x, w11, accD[2]);
            accA[3] = f2fma(mb.y, w00, accA[3]); accB[3] = f2fma(mb.y, w01, accB[3]);
            accC[3] = f2fma(mb.y, w10, accC[3]); accD[3] = f2fma(mb.y, w11, accD[3]);
        }
    }

    // ---- coord weight + scatter ----
    {
        float2 w3lo = *(const float2*)(sm + S_WX3 + c0);
        float2 w3hi = *(const float2*)(sm + S_WX3 + c1);
        u64 pc[4];
#pragma unroll
        for (int j = 0; j < 4; j++) {
            float a, b, plo, phi;
            upk(a, b, accA[j]); plo  = silu_f(a) * w3lo.x; phi  = silu_f(b) * w3lo.x;
            upk(a, b, accB[j]); plo += silu_f(a) * w3lo.y; phi += silu_f(b) * w3lo.y;
            upk(a, b, accC[j]); plo += silu_f(a) * w3hi.x; phi += silu_f(b) * w3hi.x;
            upk(a, b, accD[j]); plo += silu_f(a) * w3hi.y; phi += silu_f(b) * w3hi.y;
            pc[j] = pk(plo, phi);
        }
#pragma unroll
        for (int msk = 16; msk > 0; msk >>= 1)
#pragma unroll
            for (int j = 0; j < 4; j++)
                pc[j] = f2add(pc[j], __shfl_xor_sync(0xffffffffu, pc[j], msk));
        if (lane < 8) {
            int el = eg * 8 + lane;
            float s0, s1; upk(s0, s1, pc[lane >> 1]);
            float s = (lane & 1) ? s1 : s0;
            float cw = tanhf(s) * 2.5f;
            int d = sDst[el];
            atomicAdd(&g_coord[d * 3 + 0], sm[S_DIFFN + 0 * 64 + el] * cw);
            atomicAdd(&g_coord[d * 3 + 1], sm[S_DIFFN + 1 * 64 + el] * cw);
            atomicAdd(&g_coord[d * 3 + 2], sm[S_DIFFN + 2 * 64 + el] * cw);
        }
    }
}

// ---------------- phi_h + output assembly (streaming, batched L2 weight loads) ----------------
#define N_INT   0                      // sInT: 256 x NBP
#define N_HID   (N_INT + 256*NBP)      // sHidT: 128 x NBP
#define NODE_SMEM_FLOATS (N_HID + 128*NBP)
#define NODE_SMEM_BYTES  (NODE_SMEM_FLOATS * 4)

__global__ __launch_bounds__(256, 4)
void node_out_kernel(const float* __restrict__ h, const float* __restrict__ x,
                     const float* __restrict__ Wh_w1, const float* __restrict__ Wh_b1,
                     const float* __restrict__ Wh_w2, const float* __restrict__ Wh_b2,
                     float* __restrict__ out)
{
    extern __shared__ float sm[];
    int tid = threadIdx.x;
    int n0 = blockIdx.x * NB;

    {
        int k = tid;
#pragma unroll 4
        for (int j = 0; j < NB; j++) {
            int n = n0 + j;
            float v = 0.f;
            if (n < NN) {
                v = (k < 128) ? h[(size_t)n * HH + k]
                              : g_msg[(size_t)n * HH + (k - 128)];
            }
            sm[N_INT + k * NBP + j] = v;
        }
    }
    __syncthreads();

    int cidx = tid & 63, grp = tid >> 6;
    int c0 = 2 * cidx, jb = grp * 8;

    u64 acc0[4], acc1[4];
    {
        float2 bb = __ldg((const float2*)(Wh_b1 + c0));
        u64 p0 = pk(bb.x, bb.x), p1 = pk(bb.y, bb.y);
#pragma unroll
        for (int q = 0; q < 4; q++) { acc0[q] = p0; acc1[q] = p1; }
    }
    {
        const float2* wbase = (const float2*)(Wh_w1 + c0);
        const float* mbase = sm + N_INT + jb;
        for (int k0 = 0; k0 < 256; k0 += 4) {
            // batch 4 weight loads up front (MLP=4 over L2)
            float2 w0 = __ldg(wbase + (k0 + 0) * 64);
            float2 w1 = __ldg(wbase + (k0 + 1) * 64);
            float2 w2 = __ldg(wbase + (k0 + 2) * 64);
            float2 w3 = __ldg(wbase + (k0 + 3) * 64);
            float2 wk[4] = {w0, w1, w2, w3};
#pragma unroll
            for (int i = 0; i < 4; i++) {
                u64 ww0 = pk(wk[i].x, wk[i].x), ww1 = pk(wk[i].y, wk[i].y);
                const ulonglong2* mp = (const ulonglong2*)(mbase + (k0 + i) * NBP);
                ulonglong2 m0 = mp[0];
                acc0[0] = f2fma(m0.x, ww0, acc0[0]); acc1[0] = f2fma(m0.x, ww1, acc1[0]);
                acc0[1] = f2fma(m0.y, ww0, acc0[1]); acc1[1] = f2fma(m0.y, ww1, acc1[1]);
                ulonglong2 m1 = mp[1];
                acc0[2] = f2fma(m1.x, ww0, acc0[2]); acc1[2] = f2fma(m1.x, ww1, acc1[2]);
                acc0[3] = f2fma(m1.y, ww0, acc0[3]); acc1[3] = f2fma(m1.y, ww1, acc1[3]);
            }
        }
    }
#pragma unroll
    for (int q = 0; q < 4; q++) {
        float a, b;
        upk(a, b, acc0[q]);
        *(u64*)(sm + N_HID + c0 * NBP + jb + 2 * q) = pk(silu_f(a), silu_f(b));
        upk(a, b, acc1[q]);
        *(u64*)(sm + N_HID + (c0 + 1) * NBP + jb + 2 * q) = pk(silu_f(a), silu_f(b));
    }
    __syncthreads();

    u64 acc2[4], acc3[4];
    {
        float2 bb = __ldg((const float2*)(Wh_b2 + c0));
        u64 p0 = pk(bb.x, bb.x), p1 = pk(bb.y, bb.y);
#pragma unroll
        for (int q = 0; q < 4; q++) { acc2[q] = p0; acc3[q] = p1; }
    }
    {
        const float2* wbase = (const float2*)(Wh_w2 + c0);
        const float* mbase = sm + N_HID + jb;
        for (int k0 = 0; k0 < 128; k0 += 4) {
            float2 w0 = __ldg(wbase + (k0 + 0) * 64);
            float2 w1 = __ldg(wbase + (k0 + 1) * 64);
            float2 w2 = __ldg(wbase + (k0 + 2) * 64);
            float2 w3 = __ldg(wbase + (k0 + 3) * 64);
            float2 wk[4] = {w0, w1, w2, w3};
#pragma unroll
            for (int i = 0; i < 4; i++) {
                u64 ww0 = pk(wk[i].x, wk[i].x), ww1 = pk(wk[i].y, wk[i].y);
                const ulonglong2* mp = (const ulonglong2*)(mbase + (k0 + i) * NBP);
                ulonglong2 m0 = mp[0];
                acc2[0] = f2fma(m0.x, ww0, acc2[0]); acc3[0] = f2fma(m0.x, ww1, acc3[0]);
                acc2[1] = f2fma(m0.y, ww0, acc2[1]); acc3[1] = f2fma(m0.y, ww1, acc3[1]);
                ulonglong2 m1 = mp[1];
                acc2[2] = f2fma(m1.x, ww0, acc2[2]); acc3[2] = f2fma(m1.x, ww1, acc3[2]);
                acc2[3] = f2fma(m1.y, ww0, acc2[3]); acc3[3] = f2fma(m1.y, ww1, acc3[3]);
            }
        }
    }
#pragma unroll
    for (int q = 0; q < 4; q++) {
        float a0, b0, a1, b1;
        upk(a0, b0, acc2[q]);
        upk(a1, b1, acc3[q]);
        int na = n0 + jb + 2 * q, nb2 = na + 1;
        if (na < NN) {
            float2 hv = *(const float2*)(h + (size_t)na * HH + c0);
            *(float2*)(out + (size_t)na * HH + c0) = make_float2(hv.x + a0, hv.y + a1);
        }
        if (nb2 < NN) {
            float2 hv = *(const float2*)(h + (size_t)nb2 * HH + c0);
            *(float2*)(out + (size_t)nb2 * HH + c0) = make_float2(hv.x + b0, hv.y + b1);
        }
    }
    if (tid < NB * 3) {
        int n = n0 + tid / 3, c = tid % 3;
        if (n < NN)
            out[(size_t)NN * HH + n * 3 + c] = x[n * 3 + c] + g_coord[n * 3 + c];
    }
}

// ---------------- launch ----------------
extern "C" void kernel_launch(void* const* d_in, const int* in_sizes, int n_in,
                              void* d_out, int out_size) {
    const float* h         = (const float*)d_in[0];
    const float* x         = (const float*)d_in[1];
    const void*  ei        = d_in[2];
    const float* edge_attr = (const float*)d_in[3];
    const float* t_emb     = (const float*)d_in[4];
    const float* We_w1     = (const float*)d_in[5];
    const float* We_b1     = (const float*)d_in[6];
    const float* We_w2     = (const float*)d_in[7];
    const float* We_b2     = (const float*)d_in[8];
    const float* Watt_w    = (const float*)d_in[9];
    const float* Watt_b    = (const float*)d_in[10];
    const float* Wx_w1     = (const float*)d_in[11];
    const float* Wx_b1     = (const float*)d_in[12];
    const float* Wx_w2     = (const float*)d_in[13];
    const float* Wx_b2     = (const float*)d_in[14];
    const float* Wx_w3     = (const float*)d_in[15];
    const float* Wh_w1     = (const float*)d_in[16];
    const float* Wh_b1     = (const float*)d_in[17];
    const float* Wh_w2     = (const float*)d_in[18];
    const float* Wh_b2     = (const float*)d_in[19];
    float* out = (float*)d_out;

    cudaFuncSetAttribute(edge_kernel, cudaFuncAttributeMaxDynamicSharedMemorySize, EDGE_SMEM_BYTES);
    cudaFuncSetAttribute(node_out_kernel, cudaFuncAttributeMaxDynamicSharedMemorySize, NODE_SMEM_BYTES);

    int eblocks = NE / ET;
    int nblocks = (NN + NB - 1) / NB;

    detect_kernel<<<1, 256>>>(ei);
    precompute_kernel<<<NN / PC_NB, 128>>>(h, t_emb, We_w1, We_b1, Wx_w1, Wx_b1);
    edge_kernel<<<eblocks, 256, EDGE_SMEM_BYTES>>>(x, ei, edge_attr, We_w1, Wx_w1,
                                                   We_w2, We_b2, Watt_w, Watt_b,
                                                   Wx_w2, Wx_b2, Wx_w3);
    node_out_kernel<<<nblocks, 256, NODE_SMEM_BYTES>>>(h, x, Wh_w1, Wh_b1, Wh_w2, Wh_b2, out);
}